// round 4
// baseline (speedup 1.0000x reference)
#include <cuda_runtime.h>
#include <math.h>
#include <stdint.h>

// HashGrid2D with Morton bucketing:
//  1) counting-sort points by 16-bit Morton key (256x256 grid)
//  2) main kernel: warp = 32 spatially-adjacent points at ONE level
//     -> gather addresses collide within each LDG -> far fewer L1 wavefronts
//  3) remap kernel scatters results back to original point order.

#define N_LEVELS 16
#define TBITS    19
#define TSIZE    (1u << TBITS)
#define HMASK    (TSIZE - 1u)
#define PRIME_Y  2654435761u

#define MAXN     1048576
#define NBINS    65536

struct ScaleArr { float s[N_LEVELS]; };

// -------- scratch (static device globals; no runtime allocation) --------
__device__ int    d_hist[NBINS];
__device__ float4 d_pts[MAXN];                      // (x, y, g-as-bits, orig_p-as-bits)
__device__ float2 d_outs[(size_t)N_LEVELS * MAXN];  // level-major sorted results

// -------- morton --------
__device__ __forceinline__ unsigned part1by1(unsigned v) {
    v &= 0xffffu;
    v = (v | (v << 8)) & 0x00FF00FFu;
    v = (v | (v << 4)) & 0x0F0F0F0Fu;
    v = (v | (v << 2)) & 0x33333333u;
    v = (v | (v << 1)) & 0x55555555u;
    return v;
}
__device__ __forceinline__ unsigned morton_key(float2 xy) {
    unsigned mx = (unsigned)(xy.x * 256.0f); if (mx > 255u) mx = 255u;
    unsigned my = (unsigned)(xy.y * 256.0f); if (my > 255u) my = 255u;
    return part1by1(mx) | (part1by1(my) << 1);
}

// -------- pass 0: zero histogram --------
__global__ void zero_hist_kernel() {
    int t = blockIdx.x * blockDim.x + threadIdx.x;
    if (t < NBINS) d_hist[t] = 0;
}

// -------- pass 1: histogram --------
__global__ void hist_kernel(const float2* __restrict__ x, int N) {
    int p = blockIdx.x * blockDim.x + threadIdx.x;
    if (p >= N) return;
    atomicAdd(&d_hist[morton_key(__ldg(&x[p]))], 1);
}

// -------- pass 2: exclusive scan of 65536 bins (single block, 1024 thr) --------
__global__ void __launch_bounds__(1024) scan_kernel() {
    __shared__ int sums[1024];
    const int tid  = threadIdx.x;
    const int base = tid * (NBINS / 1024);   // 64 bins per thread

    int s = 0;
    #pragma unroll 4
    for (int k = 0; k < NBINS / 1024; k++) s += d_hist[base + k];
    sums[tid] = s;
    __syncthreads();

    // Hillis-Steele inclusive scan on 1024 sums
    for (int d = 1; d < 1024; d <<= 1) {
        int v = (tid >= d) ? sums[tid - d] : 0;
        __syncthreads();
        sums[tid] += v;
        __syncthreads();
    }
    int running = (tid == 0) ? 0 : sums[tid - 1];   // exclusive offset

    #pragma unroll 4
    for (int k = 0; k < NBINS / 1024; k++) {
        int v = d_hist[base + k];
        d_hist[base + k] = running;
        running += v;
    }
}

// -------- pass 3: scatter into sorted order --------
__global__ void scatter_kernel(const float2* __restrict__ x,
                               const int* __restrict__ gidx, int N) {
    int p = blockIdx.x * blockDim.x + threadIdx.x;
    if (p >= N) return;
    float2 xy = __ldg(&x[p]);
    int g     = __ldg(&gidx[p]);
    int pos   = atomicAdd(&d_hist[morton_key(xy)], 1);
    d_pts[pos] = make_float4(xy.x, xy.y, __int_as_float(g), __int_as_float(p));
}

// -------- pass 4: main gather kernel (level-uniform warps) --------
__global__ void __launch_bounds__(256) gather_kernel(
    const float2* __restrict__ feat, int N, ScaleArr sc)
{
    const int i     = blockIdx.x * blockDim.x + threadIdx.x;  // sorted point idx
    const int level = blockIdx.y;
    if (i >= N) return;

    const float4 pt = d_pts[i];
    const int g     = __float_as_int(pt.z);

    const float s  = sc.s[level];
    const float px = pt.x * s;
    const float py = pt.y * s;
    const float fx = floorf(px);
    const float fy = floorf(py);
    const float wx = px - fx;
    const float wy = py - fy;
    const unsigned ix = (unsigned)(int)fx;
    const unsigned iy = (unsigned)(int)fy;

    const float2* __restrict__ base =
        feat + ((size_t)(g * N_LEVELS + level) << TBITS);

    const unsigned hy0 = iy * PRIME_Y;
    const unsigned hy1 = (iy + 1u) * PRIME_Y;
    const unsigned h00 = (ix ^ hy0) & HMASK;
    const unsigned h01 = (ix ^ hy1) & HMASK;

    float2 f00, f10, f01, f11;
    if ((ix & 1u) == 0u) {
        const float4 q0 = __ldg((const float4*)base + (h00 >> 1));
        const float4 q1 = __ldg((const float4*)base + (h01 >> 1));
        if (h00 & 1u) { f00 = make_float2(q0.z, q0.w); f10 = make_float2(q0.x, q0.y); }
        else          { f00 = make_float2(q0.x, q0.y); f10 = make_float2(q0.z, q0.w); }
        if (h01 & 1u) { f01 = make_float2(q1.z, q1.w); f11 = make_float2(q1.x, q1.y); }
        else          { f01 = make_float2(q1.x, q1.y); f11 = make_float2(q1.z, q1.w); }
    } else {
        const unsigned h10 = ((ix + 1u) ^ hy0) & HMASK;
        const unsigned h11 = ((ix + 1u) ^ hy1) & HMASK;
        f00 = __ldg(base + h00);
        f10 = __ldg(base + h10);
        f01 = __ldg(base + h01);
        f11 = __ldg(base + h11);
    }

    const float w00 = (1.0f - wx) * (1.0f - wy);
    const float w10 = wx * (1.0f - wy);
    const float w01 = (1.0f - wx) * wy;
    const float w11 = wx * wy;

    float2 o;
    o.x = w00 * f00.x + w10 * f10.x + w01 * f01.x + w11 * f11.x;
    o.y = w00 * f00.y + w10 * f10.y + w01 * f01.y + w11 * f11.y;

    d_outs[(size_t)level * N + i] = o;   // coalesced
}

// -------- pass 5: remap to original order --------
// block = 256 threads handles 32 sorted points.
__global__ void __launch_bounds__(256) remap_kernel(float4* __restrict__ out4, int N) {
    __shared__ float2 sm[32][N_LEVELS + 1];   // +1 pad vs bank conflicts

    const int i0 = blockIdx.x * 32;
    const int t  = threadIdx.x;

    // load: 32 points x 16 levels from level-major scratch, coalesced
    {
        const int l0 = t >> 5;       // 0..7
        const int j  = t & 31;       // point within block
        #pragma unroll
        for (int c = 0; c < 2; c++) {
            const int l = l0 + c * 8;
            const int i = i0 + j;
            if (i < N) sm[j][l] = d_outs[(size_t)l * N + i];
        }
    }
    __syncthreads();

    // write: 8 lanes per point -> each STG.128 covers 4 points = 4 lines
    {
        const int j = t >> 3;        // 0..31 point within block
        const int q = t & 7;         // float4 index within point (0..7)
        const int i = i0 + j;
        if (i < N) {
            const int p_orig = __float_as_int(d_pts[i].w);
            const float2 a = sm[j][2 * q];
            const float2 b = sm[j][2 * q + 1];
            out4[(size_t)p_orig * 8 + q] = make_float4(a.x, a.y, b.x, b.y);
        }
    }
}

// -------- fallback (N > MAXN): R3 flat paired kernel --------
__global__ void __launch_bounds__(256) hashgrid2d_paired_kernel(
    const float2* __restrict__ x, const float2* __restrict__ feat,
    const int* __restrict__ gidx, float2* __restrict__ out,
    int n_total, ScaleArr sc)
{
    int t = blockIdx.x * blockDim.x + threadIdx.x;
    if (t >= n_total) return;
    int level = t & 15, p = t >> 4;
    float2 xy = __ldg(&x[p]);
    int g = __ldg(&gidx[p]);
    float s = sc.s[level];
    float px = xy.x * s, py = xy.y * s;
    float fx = floorf(px), fy = floorf(py);
    float wx = px - fx, wy = py - fy;
    unsigned ix = (unsigned)(int)fx, iy = (unsigned)(int)fy;
    const float2* __restrict__ base = feat + ((size_t)(g * N_LEVELS + level) << TBITS);
    unsigned hy0 = iy * PRIME_Y, hy1 = (iy + 1u) * PRIME_Y;
    unsigned h00 = (ix ^ hy0) & HMASK, h01 = (ix ^ hy1) & HMASK;
    float2 f00, f10, f01, f11;
    if ((ix & 1u) == 0u) {
        float4 q0 = __ldg((const float4*)base + (h00 >> 1));
        float4 q1 = __ldg((const float4*)base + (h01 >> 1));
        if (h00 & 1u) { f00 = make_float2(q0.z, q0.w); f10 = make_float2(q0.x, q0.y); }
        else          { f00 = make_float2(q0.x, q0.y); f10 = make_float2(q0.z, q0.w); }
        if (h01 & 1u) { f01 = make_float2(q1.z, q1.w); f11 = make_float2(q1.x, q1.y); }
        else          { f01 = make_float2(q1.x, q1.y); f11 = make_float2(q1.z, q1.w); }
    } else {
        unsigned h10 = ((ix + 1u) ^ hy0) & HMASK;
        unsigned h11 = ((ix + 1u) ^ hy1) & HMASK;
        f00 = __ldg(base + h00); f10 = __ldg(base + h10);
        f01 = __ldg(base + h01); f11 = __ldg(base + h11);
    }
    float w00 = (1.0f - wx) * (1.0f - wy), w10 = wx * (1.0f - wy);
    float w01 = (1.0f - wx) * wy,          w11 = wx * wy;
    float2 o;
    o.x = w00 * f00.x + w10 * f10.x + w01 * f01.x + w11 * f11.x;
    o.y = w00 * f00.y + w10 * f10.y + w01 * f01.y + w11 * f11.y;
    out[t] = o;
}

extern "C" void kernel_launch(void* const* d_in, const int* in_sizes, int n_in,
                              void* d_out, int out_size)
{
    const float2* x    = (const float2*)d_in[0];
    const float2* feat = (const float2*)d_in[1];
    const int*    gidx = (const int*)d_in[2];

    int N = in_sizes[0] / 2;

    ScaleArr sc;
    double bw = exp((log(512.0) - log(16.0)) / (double)(N_LEVELS - 1));
    for (int i = 0; i < N_LEVELS; i++) {
        int res = (int)(16.0 * pow(bw, (double)i));
        sc.s[i] = (float)(res - 1);
    }

    if (N > MAXN) {
        int n_total = N * N_LEVELS;
        hashgrid2d_paired_kernel<<<(n_total + 255) / 256, 256>>>(
            x, feat, gidx, (float2*)d_out, n_total, sc);
        return;
    }

    zero_hist_kernel<<<(NBINS + 255) / 256, 256>>>();
    hist_kernel<<<(N + 255) / 256, 256>>>(x, N);
    scan_kernel<<<1, 1024>>>();
    scatter_kernel<<<(N + 255) / 256, 256>>>(x, gidx, N);

    dim3 ggrid((N + 255) / 256, N_LEVELS);
    gather_kernel<<<ggrid, 256>>>(feat, N, sc);

    remap_kernel<<<(N + 31) / 32, 256>>>((float4*)d_out, N);
}

// round 5
// speedup vs baseline: 1.9886x; 1.9886x over previous
#include <cuda_runtime.h>
#include <math.h>
#include <stdint.h>

// HashGrid2D, Morton-bucketed, fully fused:
//   zero -> hist(ILP4) -> scanA(64x1024) -> scanB(64) -> scatter(ILP4)
//   -> fused gather+writeback (warp = one level x 32 adjacent points,
//      smem-staged transpose, direct coalesced store to out[p_orig]).

#define N_LEVELS 16
#define TBITS    19
#define TSIZE    (1u << TBITS)
#define HMASK    (TSIZE - 1u)
#define PRIME_Y  2654435761u

#define MAXN     1048576
#define NBINS    65536
#define NBLK_SC  64            // scan blocks (NBINS / 1024)

struct ScaleArr { float s[N_LEVELS]; };

// -------- scratch (static device globals) --------
__device__ int    d_hist[NBINS];
__device__ int    d_bsum[NBLK_SC];
__device__ float4 d_pts[MAXN];   // (x, y, g-as-bits, orig_p-as-bits)

// -------- morton --------
__device__ __forceinline__ unsigned part1by1(unsigned v) {
    v &= 0xffffu;
    v = (v | (v << 8)) & 0x00FF00FFu;
    v = (v | (v << 4)) & 0x0F0F0F0Fu;
    v = (v | (v << 2)) & 0x33333333u;
    v = (v | (v << 1)) & 0x55555555u;
    return v;
}
__device__ __forceinline__ unsigned morton_key(float xf, float yf) {
    unsigned mx = (unsigned)(xf * 256.0f); if (mx > 255u) mx = 255u;
    unsigned my = (unsigned)(yf * 256.0f); if (my > 255u) my = 255u;
    return part1by1(mx) | (part1by1(my) << 1);
}

// -------- pass 0: zero histogram --------
__global__ void zero_hist_kernel() {
    int t = blockIdx.x * blockDim.x + threadIdx.x;
    if (t < NBINS) d_hist[t] = 0;
}

// -------- pass 1: histogram, 4 points per thread --------
__global__ void hist_kernel(const float2* __restrict__ x, int N) {
    int t  = blockIdx.x * blockDim.x + threadIdx.x;
    int p0 = t * 4;
    if (p0 >= N) return;
    if (p0 + 3 < N) {
        const float4* x4 = (const float4*)x;
        float4 a = __ldg(&x4[t * 2]);
        float4 b = __ldg(&x4[t * 2 + 1]);
        atomicAdd(&d_hist[morton_key(a.x, a.y)], 1);
        atomicAdd(&d_hist[morton_key(a.z, a.w)], 1);
        atomicAdd(&d_hist[morton_key(b.x, b.y)], 1);
        atomicAdd(&d_hist[morton_key(b.z, b.w)], 1);
    } else {
        for (int k = 0; k < 4 && p0 + k < N; k++) {
            float2 xy = __ldg(&x[p0 + k]);
            atomicAdd(&d_hist[morton_key(xy.x, xy.y)], 1);
        }
    }
}

// -------- pass 2a: per-1024-chunk exclusive scan (coalesced) --------
__global__ void __launch_bounds__(1024) scanA_kernel() {
    __shared__ int sm[1024];
    const int b   = blockIdx.x;
    const int tid = threadIdx.x;
    const int idx = b * 1024 + tid;
    const int v   = d_hist[idx];
    sm[tid] = v;
    __syncthreads();
    #pragma unroll
    for (int d = 1; d < 1024; d <<= 1) {
        int u = (tid >= d) ? sm[tid - d] : 0;
        __syncthreads();
        sm[tid] += u;
        __syncthreads();
    }
    d_hist[idx] = sm[tid] - v;          // exclusive within chunk
    if (tid == 1023) d_bsum[b] = sm[tid];
}

// -------- pass 2b: scan of 64 chunk sums --------
__global__ void scanB_kernel() {
    __shared__ int sm[NBLK_SC];
    const int tid = threadIdx.x;
    const int v   = d_bsum[tid];
    sm[tid] = v;
    __syncthreads();
    #pragma unroll
    for (int d = 1; d < NBLK_SC; d <<= 1) {
        int u = (tid >= d) ? sm[tid - d] : 0;
        __syncthreads();
        sm[tid] += u;
        __syncthreads();
    }
    d_bsum[tid] = sm[tid] - v;          // exclusive chunk offsets
}

// -------- pass 3: scatter into sorted order, 4 points per thread --------
__global__ void scatter_kernel(const float2* __restrict__ x,
                               const int* __restrict__ gidx, int N) {
    int t  = blockIdx.x * blockDim.x + threadIdx.x;
    int p0 = t * 4;
    if (p0 >= N) return;
    float xs[4], ys[4];
    int   gs[4];
    int   cnt;
    if (p0 + 3 < N) {
        const float4* x4 = (const float4*)x;
        float4 a = __ldg(&x4[t * 2]);
        float4 b = __ldg(&x4[t * 2 + 1]);
        int4   g = __ldg(&((const int4*)gidx)[t]);
        xs[0]=a.x; ys[0]=a.y; xs[1]=a.z; ys[1]=a.w;
        xs[2]=b.x; ys[2]=b.y; xs[3]=b.z; ys[3]=b.w;
        gs[0]=g.x; gs[1]=g.y; gs[2]=g.z; gs[3]=g.w;
        cnt = 4;
    } else {
        cnt = N - p0;
        for (int k = 0; k < cnt; k++) {
            float2 xy = __ldg(&x[p0 + k]);
            xs[k]=xy.x; ys[k]=xy.y; gs[k]=__ldg(&gidx[p0 + k]);
        }
    }
    unsigned bin[4];
    int off[4];
    for (int k = 0; k < cnt; k++) bin[k] = morton_key(xs[k], ys[k]);
    for (int k = 0; k < cnt; k++) off[k] = d_bsum[bin[k] >> 10];
    for (int k = 0; k < cnt; k++) {
        int pos = off[k] + atomicAdd(&d_hist[bin[k]], 1);
        d_pts[pos] = make_float4(xs[k], ys[k],
                                 __int_as_float(gs[k]), __int_as_float(p0 + k));
    }
}

// -------- pass 4: fused gather + writeback --------
// block = 512 threads = 16 warps; warp w = level w for 32 adjacent sorted points.
__global__ void __launch_bounds__(512) fused_gather_kernel(
    const float2* __restrict__ feat, float2* __restrict__ out2,
    int N, ScaleArr sc)
{
    __shared__ float2 smres[N_LEVELS][33];   // [level][point], padded
    __shared__ int    sporig[32];

    const int i0    = blockIdx.x * 32;
    const int warp  = threadIdx.x >> 5;      // level
    const int lane  = threadIdx.x & 31;      // point within group
    const int i     = i0 + lane;
    const bool valid = (i < N);

    float4 pt = valid ? d_pts[i] : make_float4(0.f, 0.f, 0.f, 0.f);
    if (warp == 0 && valid) sporig[lane] = __float_as_int(pt.w);

    const int   g  = __float_as_int(pt.z);
    const float s  = sc.s[warp];
    const float px = pt.x * s;
    const float py = pt.y * s;
    const float fx = floorf(px);
    const float fy = floorf(py);
    const float wx = px - fx;
    const float wy = py - fy;
    const unsigned ix = (unsigned)(int)fx;
    const unsigned iy = (unsigned)(int)fy;

    const float2* __restrict__ base =
        feat + ((size_t)(g * N_LEVELS + warp) << TBITS);

    const unsigned hy0 = iy * PRIME_Y;
    const unsigned hy1 = (iy + 1u) * PRIME_Y;
    const unsigned h00 = (ix ^ hy0) & HMASK;
    const unsigned h01 = (ix ^ hy1) & HMASK;

    float2 f00, f10, f01, f11;
    if ((ix & 1u) == 0u) {
        const float4 q0 = __ldg((const float4*)base + (h00 >> 1));
        const float4 q1 = __ldg((const float4*)base + (h01 >> 1));
        if (h00 & 1u) { f00 = make_float2(q0.z, q0.w); f10 = make_float2(q0.x, q0.y); }
        else          { f00 = make_float2(q0.x, q0.y); f10 = make_float2(q0.z, q0.w); }
        if (h01 & 1u) { f01 = make_float2(q1.z, q1.w); f11 = make_float2(q1.x, q1.y); }
        else          { f01 = make_float2(q1.x, q1.y); f11 = make_float2(q1.z, q1.w); }
    } else {
        const unsigned h10 = ((ix + 1u) ^ hy0) & HMASK;
        const unsigned h11 = ((ix + 1u) ^ hy1) & HMASK;
        f00 = __ldg(base + h00);
        f10 = __ldg(base + h10);
        f01 = __ldg(base + h01);
        f11 = __ldg(base + h11);
    }

    const float w00 = (1.0f - wx) * (1.0f - wy);
    const float w10 = wx * (1.0f - wy);
    const float w01 = (1.0f - wx) * wy;
    const float w11 = wx * wy;

    float2 o;
    o.x = w00 * f00.x + w10 * f10.x + w01 * f01.x + w11 * f11.x;
    o.y = w00 * f00.y + w10 * f10.y + w01 * f01.y + w11 * f11.y;

    smres[warp][lane] = o;
    __syncthreads();

    // writeback: thread t -> point j = t>>4, level l = t&15
    const int j = threadIdx.x >> 4;
    const int l = threadIdx.x & 15;
    if (i0 + j < N) {
        const int p_orig = sporig[j];
        out2[(size_t)p_orig * N_LEVELS + l] = smres[l][j];
    }
}

// -------- fallback (N > MAXN): flat paired kernel --------
__global__ void __launch_bounds__(256) hashgrid2d_paired_kernel(
    const float2* __restrict__ x, const float2* __restrict__ feat,
    const int* __restrict__ gidx, float2* __restrict__ out,
    int n_total, ScaleArr sc)
{
    int t = blockIdx.x * blockDim.x + threadIdx.x;
    if (t >= n_total) return;
    int level = t & 15, p = t >> 4;
    float2 xy = __ldg(&x[p]);
    int g = __ldg(&gidx[p]);
    float s = sc.s[level];
    float px = xy.x * s, py = xy.y * s;
    float fx = floorf(px), fy = floorf(py);
    float wx = px - fx, wy = py - fy;
    unsigned ix = (unsigned)(int)fx, iy = (unsigned)(int)fy;
    const float2* __restrict__ base = feat + ((size_t)(g * N_LEVELS + level) << TBITS);
    unsigned hy0 = iy * PRIME_Y, hy1 = (iy + 1u) * PRIME_Y;
    unsigned h00 = (ix ^ hy0) & HMASK, h01 = (ix ^ hy1) & HMASK;
    float2 f00, f10, f01, f11;
    if ((ix & 1u) == 0u) {
        float4 q0 = __ldg((const float4*)base + (h00 >> 1));
        float4 q1 = __ldg((const float4*)base + (h01 >> 1));
        if (h00 & 1u) { f00 = make_float2(q0.z, q0.w); f10 = make_float2(q0.x, q0.y); }
        else          { f00 = make_float2(q0.x, q0.y); f10 = make_float2(q0.z, q0.w); }
        if (h01 & 1u) { f01 = make_float2(q1.z, q1.w); f11 = make_float2(q1.x, q1.y); }
        else          { f01 = make_float2(q1.x, q1.y); f11 = make_float2(q1.z, q1.w); }
    } else {
        unsigned h10 = ((ix + 1u) ^ hy0) & HMASK;
        unsigned h11 = ((ix + 1u) ^ hy1) & HMASK;
        f00 = __ldg(base + h00); f10 = __ldg(base + h10);
        f01 = __ldg(base + h01); f11 = __ldg(base + h11);
    }
    float w00 = (1.0f - wx) * (1.0f - wy), w10 = wx * (1.0f - wy);
    float w01 = (1.0f - wx) * wy,          w11 = wx * wy;
    float2 o;
    o.x = w00 * f00.x + w10 * f10.x + w01 * f01.x + w11 * f11.x;
    o.y = w00 * f00.y + w10 * f10.y + w01 * f01.y + w11 * f11.y;
    out[t] = o;
}

extern "C" void kernel_launch(void* const* d_in, const int* in_sizes, int n_in,
                              void* d_out, int out_size)
{
    const float2* x    = (const float2*)d_in[0];
    const float2* feat = (const float2*)d_in[1];
    const int*    gidx = (const int*)d_in[2];

    int N = in_sizes[0] / 2;

    ScaleArr sc;
    double bw = exp((log(512.0) - log(16.0)) / (double)(N_LEVELS - 1));
    for (int i = 0; i < N_LEVELS; i++) {
        int res = (int)(16.0 * pow(bw, (double)i));
        sc.s[i] = (float)(res - 1);
    }

    if (N > MAXN) {
        int n_total = N * N_LEVELS;
        hashgrid2d_paired_kernel<<<(n_total + 255) / 256, 256>>>(
            x, feat, gidx, (float2*)d_out, n_total, sc);
        return;
    }

    int nquads = (N + 3) / 4;
    zero_hist_kernel<<<NBINS / 256, 256>>>();
    hist_kernel<<<(nquads + 255) / 256, 256>>>(x, N);
    scanA_kernel<<<NBLK_SC, 1024>>>();
    scanB_kernel<<<1, NBLK_SC>>>();
    scatter_kernel<<<(nquads + 255) / 256, 256>>>(x, gidx, N);

    fused_gather_kernel<<<(N + 31) / 32, 512>>>(feat, (float2*)d_out, N, sc);
}